// round 13
// baseline (speedup 1.0000x reference)
#include <cuda_runtime.h>
#include <cuda_fp16.h>
#include <math.h>
#include <stdint.h>

#define SEQ    2048
#define BATCH  2
#define DMODEL 1024
#define NH     16
#define HD     64
#define DFF    4096
#define ROWS   (SEQ*BATCH)   // 4096

// ---------------- scratch (device globals; no allocation allowed) ----------
__device__ __half g_h16  [ROWS*DMODEL];      // LN1 out (fp16)
__device__ __half g_q16  [ROWS*DMODEL];      // Q (fp16, pre-scaled by 1/8)
__device__ __half g_kv16 [2*BATCH*NH*SEQ*HD];// K,V fp16 copy [2,B,H,L,hd]
__device__ __half g_attn16[ROWS*DMODEL];     // attention out (fp16)
__device__ float  g_x1   [ROWS*DMODEL];      // x + attn_proj (fp32)
__device__ __half g_h2_16[ROWS*DMODEL];      // LN2 out (fp16)
__device__ __half g_m16  [ROWS*DFF];         // gelu(fc) out (fp16)
// transposed fp16 weights [N,K]
__device__ __half g_wt_attn[3*DMODEL*DMODEL];
__device__ __half g_wt_proj[DMODEL*DMODEL];
__device__ __half g_wt_fc  [DFF*DMODEL];
__device__ __half g_wt_out [DMODEL*DFF];

// ---------------- helpers ----------------------------------------------------
__device__ __forceinline__ uint32_t smem_u32(const void* p)
{
    return (uint32_t)__cvta_generic_to_shared(p);
}

__device__ __forceinline__ void cp16(uint32_t dst, const void* src)
{
    asm volatile("cp.async.cg.shared.global [%0], [%1], 16;" :: "r"(dst), "l"(src) : "memory");
}

__device__ __forceinline__ void ldsm_x4(uint32_t* r, uint32_t addr)
{
    asm volatile("ldmatrix.sync.aligned.m8n8.x4.shared.b16 {%0,%1,%2,%3}, [%4];"
                 : "=r"(r[0]), "=r"(r[1]), "=r"(r[2]), "=r"(r[3]) : "r"(addr));
}

__device__ __forceinline__ void ldsm_x4t(uint32_t* r, uint32_t addr)
{
    asm volatile("ldmatrix.sync.aligned.m8n8.x4.trans.shared.b16 {%0,%1,%2,%3}, [%4];"
                 : "=r"(r[0]), "=r"(r[1]), "=r"(r[2]), "=r"(r[3]) : "r"(addr));
}

__device__ __forceinline__ void mma16816(float* c, const uint32_t* a, const uint32_t* b)
{
    asm volatile(
        "mma.sync.aligned.m16n8k16.row.col.f32.f16.f16.f32 "
        "{%0,%1,%2,%3}, {%4,%5,%6,%7}, {%8,%9}, {%0,%1,%2,%3};\n"
        : "+f"(c[0]), "+f"(c[1]), "+f"(c[2]), "+f"(c[3])
        : "r"(a[0]), "r"(a[1]), "r"(a[2]), "r"(a[3]),
          "r"(b[0]), "r"(b[1]));
}

__device__ __forceinline__ uint32_t pack_h2(float a, float b)
{
    __half2 h = __floats2half2_rn(a, b);
    return *reinterpret_cast<uint32_t*>(&h);
}

__device__ __forceinline__ float gelu_f(float v)
{
    float c = v + 0.044715f * v * v * v;
    return 0.5f * v * (1.0f + tanhf(0.7978845608028654f * c));
}

// ---------------- batched weight transpose+convert --------------------------
#define TT_TOTAL 12288
__global__ void transpose_all(const float* __restrict__ w0, const float* __restrict__ w1,
                              const float* __restrict__ w2, const float* __restrict__ w3,
                              __half* __restrict__ t0, __half* __restrict__ t1,
                              __half* __restrict__ t2, __half* __restrict__ t3)
{
    __shared__ float t[32][33];
    int tb = blockIdx.x;
    const float* W; __half* Wt; int K, N, ntx, local;
    if (tb < 3072)      { W = w0; Wt = t0; K = DMODEL; N = 3*DMODEL; ntx = 96;  local = tb; }
    else if (tb < 4096) { W = w1; Wt = t1; K = DMODEL; N = DMODEL;   ntx = 32;  local = tb - 3072; }
    else if (tb < 8192) { W = w2; Wt = t2; K = DMODEL; N = DFF;      ntx = 128; local = tb - 4096; }
    else                { W = w3; Wt = t3; K = DFF;    N = DMODEL;   ntx = 32;  local = tb - 8192; }
    int n0 = (local % ntx) * 32, k0 = (local / ntx) * 32;
    int tx = threadIdx.x, ty = threadIdx.y;
    #pragma unroll
    for (int d = 0; d < 32; d += 8)
        t[ty + d][tx] = W[(size_t)(k0 + ty + d) * N + n0 + tx];
    __syncthreads();
    #pragma unroll
    for (int d = 0; d < 32; d += 8)
        Wt[(size_t)(n0 + ty + d) * K + k0 + tx] = __float2half_rn(t[tx][ty + d]);
}

// ---------------- LayerNorm: one CTA per row, fp16 output ------------------
__global__ void ln_kernel(const float* __restrict__ x,
                          const float* __restrict__ g,
                          const float* __restrict__ b,
                          __half* __restrict__ y)
{
    int row = blockIdx.x;
    int tid = threadIdx.x;
    const float4* xr = reinterpret_cast<const float4*>(x + (size_t)row * DMODEL);
    float4 v = xr[tid];

    __shared__ float red[8];
    __shared__ float stat[2];

    float s = v.x + v.y + v.z + v.w;
    #pragma unroll
    for (int o = 16; o; o >>= 1) s += __shfl_xor_sync(0xffffffffu, s, o);
    if ((tid & 31) == 0) red[tid >> 5] = s;
    __syncthreads();
    if (tid == 0) {
        float t = 0.f;
        #pragma unroll
        for (int i = 0; i < 8; i++) t += red[i];
        stat[0] = t * (1.0f / DMODEL);
    }
    __syncthreads();
    float mu = stat[0];

    float dx = v.x - mu, dy = v.y - mu, dz = v.z - mu, dw = v.w - mu;
    float s2 = dx*dx + dy*dy + dz*dz + dw*dw;
    #pragma unroll
    for (int o = 16; o; o >>= 1) s2 += __shfl_xor_sync(0xffffffffu, s2, o);
    if ((tid & 31) == 0) red[tid >> 5] = s2;
    __syncthreads();
    if (tid == 0) {
        float t = 0.f;
        #pragma unroll
        for (int i = 0; i < 8; i++) t += red[i];
        stat[1] = rsqrtf(t * (1.0f / DMODEL) + 1e-5f);
    }
    __syncthreads();
    float rstd = stat[1];

    const float4* gr = reinterpret_cast<const float4*>(g);
    const float4* br = reinterpret_cast<const float4*>(b);
    float4 gv = gr[tid], bv = br[tid];
    __half2 p0 = __floats2half2_rn(dx * rstd * gv.x + bv.x, dy * rstd * gv.y + bv.y);
    __half2 p1 = __floats2half2_rn(dz * rstd * gv.z + bv.z, dw * rstd * gv.w + bv.w);
    __half2* yr = reinterpret_cast<__half2*>(y + (size_t)row * DMODEL);
    yr[tid * 2 + 0] = p0;
    yr[tid * 2 + 1] = p1;
}

// ---------------- fp16 mma.sync GEMM ----------------------------------------
// C[M,N] = A[M,K]f16 @ Bt[N,K]f16^T + epilogue, fp32 accum.
// 128x256 CTA tile, BK=32 halves, 5-stage cp.async ring, single sync/iter.
// 512 threads = 16 warps (2x8); warp tile 64x32 = 4m x 4n of m16n8k16.
// EPI: 0 = +bias (f32 out), 1 = +bias+res (f32 out), 2 = gelu(+bias) (f16 out)
// EPI 3 = qkv split: Q -> Ch (fp16, x0.125), K/V -> Cf (present fp32) + kvh (fp16)
#define BK        32
#define KROW      40                        // BK + 8 pad (halves); 80B stride
#define A_STAGE_B (128*KROW*2)              // 10240 bytes
#define B_STAGE_B (256*KROW*2)              // 20480 bytes
#define STAGE_B   (A_STAGE_B + B_STAGE_B)   // 30720 bytes
#define GSTAGES   5
#define GEMM_SMEM (GSTAGES*STAGE_B)         // 153600

template<int EPI>
__global__ void __launch_bounds__(512, 1)
hgemm(const __half* __restrict__ A, const __half* __restrict__ Bt,
      const float* __restrict__ bias, const float* __restrict__ res,
      float* __restrict__ Cf, __half* __restrict__ Ch,
      __half* __restrict__ kvh,
      int M, int N, int K)
{
    extern __shared__ char smem_raw[];
    uint32_t sbase = smem_u32(smem_raw);

    int tid = threadIdx.x;
    int w = tid >> 5, lane = tid & 31;
    int lr = lane >> 2, lc = lane & 3;
    int wm = w >> 3, wn = w & 7;                 // 2 x 8 warp grid
    int row0 = blockIdx.y * 128, col0 = blockIdx.x * 256;
    int KT = K / BK;

    float acc[4][4][4];
    #pragma unroll
    for (int i = 0; i < 4; ++i)
        #pragma unroll
        for (int j = 0; j < 4; ++j)
            acc[i][j][0] = acc[i][j][1] = acc[i][j][2] = acc[i][j][3] = 0.f;

    int ar = tid >> 2, seg = tid & 3;
    const char* Asrc  = (const char*)(A + (size_t)(row0 + ar) * K + seg * 8);
    const char* Bsrc0 = (const char*)(Bt + (size_t)(col0 + ar) * K + seg * 8);
    const char* Bsrc1 = (const char*)(Bt + (size_t)(col0 + ar + 128) * K + seg * 8);
    uint32_t dA  = (uint32_t)(ar * KROW + seg * 8) * 2;
    uint32_t dB1 = dA + (uint32_t)(128 * KROW) * 2;

    int g = lane >> 3;   // 0..3
    uint32_t aFrag[2], bFrag[2];
    #pragma unroll
    for (int kk = 0; kk < 2; ++kk) {
        aFrag[kk] = (uint32_t)((wm * 64 + (lane & 15)) * KROW + kk * 16 + (lane >> 4) * 8) * 2;
        bFrag[kk] = (uint32_t)A_STAGE_B +
                    (uint32_t)((wn * 32 + (g >> 1) * 8 + (lane & 7)) * KROW
                               + kk * 16 + (g & 1) * 8) * 2;
    }

    auto load_stage = [&](int slot, int kc) {
        uint32_t ab = sbase + slot * STAGE_B;
        uint32_t bb = ab + A_STAGE_B;
        size_t koff = (size_t)kc * BK * 2;
        cp16(ab + dA,  Asrc  + koff);
        cp16(bb + dA,  Bsrc0 + koff);
        cp16(bb + dB1, Bsrc1 + koff);
    };

    #pragma unroll
    for (int c = 0; c < GSTAGES - 1; ++c) {
        load_stage(c, c);
        asm volatile("cp.async.commit_group;" ::: "memory");
    }

    int use_slot = 0, ld_slot = GSTAGES - 1;
    for (int i = 0; i < KT; ++i) {
        asm volatile("cp.async.wait_group %0;" :: "n"(GSTAGES - 2) : "memory");
        __syncthreads();                           // single barrier per iter

        if (i + GSTAGES - 1 < KT)
            load_stage(ld_slot, i + GSTAGES - 1);
        asm volatile("cp.async.commit_group;" ::: "memory");

        uint32_t stg = sbase + use_slot * STAGE_B;
        #pragma unroll
        for (int kk = 0; kk < 2; ++kk) {
            uint32_t af[4][4], bf[2][4];
            #pragma unroll
            for (int mi = 0; mi < 4; ++mi)
                ldsm_x4(af[mi], stg + aFrag[kk] + (uint32_t)(mi * 16 * KROW) * 2);
            #pragma unroll
            for (int nb = 0; nb < 2; ++nb)
                ldsm_x4(bf[nb], stg + bFrag[kk] + (uint32_t)(nb * 16 * KROW) * 2);
            #pragma unroll
            for (int mi = 0; mi < 4; ++mi)
                #pragma unroll
                for (int nb = 0; nb < 2; ++nb) {
                    mma16816(acc[mi][2*nb],   af[mi], &bf[nb][0]);
                    mma16816(acc[mi][2*nb+1], af[mi], &bf[nb][2]);
                }
        }

        use_slot = (use_slot == GSTAGES - 1) ? 0 : use_slot + 1;
        ld_slot  = (ld_slot  == GSTAGES - 1) ? 0 : ld_slot  + 1;
    }

    int sect = col0 >> 10;   // EPI==3: constant per tile (256 | 1024)

    #pragma unroll
    for (int mi = 0; mi < 4; ++mi) {
        #pragma unroll
        for (int hh = 0; hh < 2; ++hh) {
            int r = row0 + wm * 64 + mi * 16 + lr + hh * 8;
            #pragma unroll
            for (int ni = 0; ni < 4; ++ni) {
                int c = col0 + wn * 32 + ni * 8 + 2 * lc;
                float2 bv = *(const float2*)&bias[c];
                float ox = acc[mi][ni][2 * hh + 0] + bv.x;
                float oy = acc[mi][ni][2 * hh + 1] + bv.y;
                if (EPI == 1) {
                    float2 rv = *(const float2*)&res[(size_t)r * N + c];
                    ox += rv.x; oy += rv.y;
                }
                if (EPI == 2) {
                    *(__half2*)&Ch[(size_t)r * N + c] =
                        __floats2half2_rn(gelu_f(ox), gelu_f(oy));
                } else if (EPI == 3) {
                    if (sect == 0) {
                        *(__half2*)&Ch[(size_t)r * DMODEL + c] =
                            __floats2half2_rn(ox * 0.125f, oy * 0.125f);
                    } else {
                        int d  = c & (DMODEL - 1);
                        int hh2 = d >> 6, hd = d & (HD - 1);
                        int l = r >> 1, bb = r & 1;
                        size_t pidx = ((((size_t)(sect - 1) * BATCH + bb) * NH + hh2) * SEQ + l) * HD + hd;
                        *(float2*)&Cf[pidx] = make_float2(ox, oy);
                        *(__half2*)&kvh[pidx] = __floats2half2_rn(ox, oy);
                    }
                } else {
                    *(float2*)&Cf[(size_t)r * N + c] = make_float2(ox, oy);
                }
            }
        }
    }
}

// ---------------- Flash attention (fp16 mma.m16n8k16, register P) ----------
// CTA: 128 queries x (head, batch), 256 threads = 8 warps; warp w owns query
// rows 16w..16w+15. K/V via triple-buffered cp.async. K and V fragments are
// fetched with x4 ldmatrix (two n-tiles per instruction) - half the LDSM issue.
#define AQP   72                         // row pitch (halves) = 144B
#define KVBUF (64*AQP)                   // halves per K (or V) tile
#define NBUF  3
#define ATTN_SMEM ((128*AQP + NBUF*2*KVBUF) * 2)
#define NKB   (SEQ/64)

__global__ void __launch_bounds__(256)
attn_kernel(const __half* __restrict__ q16, const __half* __restrict__ kv16,
            __half* __restrict__ out)
{
    extern __shared__ __half sh[];
    __half* sQ  = sh;                    // 128 x AQP
    __half* sKV = sh + 128 * AQP;        // NBUF x (K 64xAQP, V 64xAQP)

    int tid  = threadIdx.x;
    int w = tid >> 5, lane = tid & 31;
    int lr = lane >> 2, lc = lane & 3;
    int bq = blockIdx.x, h = blockIdx.y, b = blockIdx.z;

    const __half* Kg = kv16 + ((size_t)b * NH + h) * SEQ * HD;
    const __half* Vg = kv16 + (((size_t)BATCH + b) * NH + h) * SEQ * HD;

    #pragma unroll
    for (int i = 0; i < 4; ++i) {
        int ck = i * 256 + tid;
        int r = ck >> 3, seg = ck & 7;
        cp16(smem_u32(sQ + r * AQP + seg * 8),
             q16 + (((size_t)(bq * 128 + r) * BATCH + b) * DMODEL + h * HD + seg * 8));
    }
    asm volatile("cp.async.commit_group;" ::: "memory");

    auto load_kv = [&](int kb, int buf) {
        __half* Kb = sKV + buf * 2 * KVBUF;
        __half* Vb = Kb + KVBUF;
        #pragma unroll
        for (int i = 0; i < 2; ++i) {
            int ck = i * 256 + tid;
            int r = ck >> 3, seg = ck & 7;
            cp16(smem_u32(Kb + r * AQP + seg * 8),
                 Kg + (size_t)(kb * 64 + r) * HD + seg * 8);
            cp16(smem_u32(Vb + r * AQP + seg * 8),
                 Vg + (size_t)(kb * 64 + r) * HD + seg * 8);
        }
    };

    load_kv(0, 0);
    asm volatile("cp.async.commit_group;" ::: "memory");
    load_kv(1, 1);
    asm volatile("cp.async.commit_group;" ::: "memory");

    asm volatile("cp.async.wait_group 2;" ::: "memory");
    __syncthreads();
    uint32_t qa[4][4];
    #pragma unroll
    for (int kk = 0; kk < 4; ++kk)
        ldsm_x4(qa[kk], smem_u32(sQ + ((w * 16 + (lane & 15)) * AQP
                                       + kk * 16 + (lane >> 4) * 8)));

    // x4 fragment offsets (lane-group trick): g = lane>>3
    // K (B-operand, pairs of n-tiles): row = nip*16 + (g>>1)*8 + (lane&7),
    //                                  col = kk*16 + (g&1)*8
    uint32_t kOff[4], vOff[4];
    {
        int gHi = (lane >> 4);        // g>>1
        int gLo = (lane >> 3) & 1;    // g&1
        #pragma unroll
        for (int kk = 0; kk < 4; ++kk)
            kOff[kk] = (uint32_t)((gHi * 8 + (lane & 7)) * AQP + kk * 16 + gLo * 8) * 2;
        // V (trans): row = kk*16 + (g&1)*8 + (lane&7), col = nip*16 + (g>>1)*8
        #pragma unroll
        for (int kk = 0; kk < 4; ++kk)
            vOff[kk] = (uint32_t)((kk * 16 + gLo * 8 + (lane & 7)) * AQP + gHi * 8) * 2;
    }

    float mrow[2] = {-1e30f, -1e30f};
    float lrow[2] = {0.f, 0.f};
    float O[8][4];
    #pragma unroll
    for (int ni = 0; ni < 8; ++ni)
        O[ni][0] = O[ni][1] = O[ni][2] = O[ni][3] = 0.f;

    int buf = 0, nbuf = 2;
    for (int kb = 0; kb < NKB; ++kb) {
        asm volatile("cp.async.wait_group 1;" ::: "memory");
        __syncthreads();

        if (kb + 2 < NKB) load_kv(kb + 2, nbuf);
        asm volatile("cp.async.commit_group;" ::: "memory");

        uint32_t Kb = smem_u32(sKV + buf * 2 * KVBUF);
        uint32_t Vb = Kb + KVBUF * 2;

        // S = Q @ K^T : 4 kk x 4 n-pairs, x4 K loads
        float S[8][4];
        #pragma unroll
        for (int ni = 0; ni < 8; ++ni)
            S[ni][0] = S[ni][1] = S[ni][2] = S[ni][3] = 0.f;
        #pragma unroll
        for (int kk = 0; kk < 4; ++kk) {
            #pragma unroll
            for (int nip = 0; nip < 4; ++nip) {
                uint32_t kf[4];
                ldsm_x4(kf, Kb + kOff[kk] + (uint32_t)(nip * 16 * AQP) * 2);
                mma16816(S[2*nip],   qa[kk], &kf[0]);
                mma16816(S[2*nip+1], qa[kk], &kf[2]);
            }
        }

        #pragma unroll
        for (int hh = 0; hh < 2; ++hh) {
            float mx = -1e30f;
            #pragma unroll
            for (int ni = 0; ni < 8; ++ni)
                mx = fmaxf(mx, fmaxf(S[ni][2*hh], S[ni][2*hh+1]));
            mx = fmaxf(mx, __shfl_xor_sync(0xffffffffu, mx, 1));
            mx = fmaxf(mx, __shfl_xor_sync(0xffffffffu, mx, 2));
            float nm = fmaxf(mrow[hh], mx);
            float corr = __expf(mrow[hh] - nm);
            mrow[hh] = nm;
            float rs = 0.f;
            #pragma unroll
            for (int ni = 0; ni < 8; ++ni) {
                float p0 = __expf(S[ni][2*hh]   - nm);
                float p1 = __expf(S[ni][2*hh+1] - nm);
                S[ni][2*hh] = p0; S[ni][2*hh+1] = p1;
                rs += p0 + p1;
            }
            rs += __shfl_xor_sync(0xffffffffu, rs, 1);
            rs += __shfl_xor_sync(0xffffffffu, rs, 2);
            lrow[hh] = lrow[hh] * corr + rs;
            #pragma unroll
            for (int ni = 0; ni < 8; ++ni) {
                O[ni][2*hh]   *= corr;
                O[ni][2*hh+1] *= corr;
            }
        }

        // O += P @ V : x4.trans V loads (two n-tiles x both k-halves)
        #pragma unroll
        for (int kk = 0; kk < 4; ++kk) {
            uint32_t pa[4];
            pa[0] = pack_h2(S[2*kk][0],   S[2*kk][1]);
            pa[1] = pack_h2(S[2*kk][2],   S[2*kk][3]);
            pa[2] = pack_h2(S[2*kk+1][0], S[2*kk+1][1]);
            pa[3] = pack_h2(S[2*kk+1][2], S[2*kk+1][3]);
            #pragma unroll
            for (int nip = 0; nip < 4; ++nip) {
                uint32_t vf[4];
                ldsm_x4t(vf, Vb + vOff[kk] + (uint32_t)(nip * 16) * 2);
                mma16816(O[2*nip],   pa, &vf[0]);
                mma16816(O[2*nip+1], pa, &vf[2]);
            }
        }

        buf  = (buf == NBUF - 1) ? 0 : buf + 1;
        nbuf = (nbuf == NBUF - 1) ? 0 : nbuf + 1;
    }

    #pragma unroll
    for (int hh = 0; hh < 2; ++hh) {
        int r = w * 16 + lr + hh * 8;
        int l = bq * 128 + r;
        float inv = 1.0f / lrow[hh];
        __half* po = out + (size_t)(l * BATCH + b) * DMODEL + h * HD;
        #pragma unroll
        for (int ni = 0; ni < 8; ++ni)
            *(__half2*)&po[ni * 8 + 2 * lc] =
                __floats2half2_rn(O[ni][2*hh] * inv, O[ni][2*hh+1] * inv);
    }
}

// ---------------- launcher --------------------------------------------------
extern "C" void kernel_launch(void* const* d_in, const int* in_sizes, int n_in,
                              void* d_out, int out_size)
{
    const float* x      = (const float*)d_in[0];
    const float* ln1_g  = (const float*)d_in[1];
    const float* ln1_b  = (const float*)d_in[2];
    const float* w_attn = (const float*)d_in[3];
    const float* b_attn = (const float*)d_in[4];
    const float* w_proj = (const float*)d_in[5];
    const float* b_proj = (const float*)d_in[6];
    const float* ln2_g  = (const float*)d_in[7];
    const float* ln2_b  = (const float*)d_in[8];
    const float* w_fc   = (const float*)d_in[9];
    const float* b_fc   = (const float*)d_in[10];
    const float* w_out  = (const float*)d_in[11];
    const float* b_out  = (const float*)d_in[12];

    float* out     = (float*)d_out;
    float* present = out + (size_t)SEQ * BATCH * DMODEL;

    __half *h16, *q16, *kv16, *attn16, *h2_16, *m16;
    __half *wt_attn, *wt_proj, *wt_fc, *wt_out;
    float *x1;
    cudaGetSymbolAddress((void**)&h16,     g_h16);
    cudaGetSymbolAddress((void**)&q16,     g_q16);
    cudaGetSymbolAddress((void**)&kv16,    g_kv16);
    cudaGetSymbolAddress((void**)&attn16,  g_attn16);
    cudaGetSymbolAddress((void**)&x1,      g_x1);
    cudaGetSymbolAddress((void**)&h2_16,   g_h2_16);
    cudaGetSymbolAddress((void**)&m16,     g_m16);
    cudaGetSymbolAddress((void**)&wt_attn, g_wt_attn);
    cudaGetSymbolAddress((void**)&wt_proj, g_wt_proj);
    cudaGetSymbolAddress((void**)&wt_fc,   g_wt_fc);
    cudaGetSymbolAddress((void**)&wt_out,  g_wt_out);

    cudaFuncSetAttribute(attn_kernel, cudaFuncAttributeMaxDynamicSharedMemorySize, ATTN_SMEM);
    cudaFuncSetAttribute(hgemm<0>, cudaFuncAttributeMaxDynamicSharedMemorySize, GEMM_SMEM);
    cudaFuncSetAttribute(hgemm<1>, cudaFuncAttributeMaxDynamicSharedMemorySize, GEMM_SMEM);
    cudaFuncSetAttribute(hgemm<2>, cudaFuncAttributeMaxDynamicSharedMemorySize, GEMM_SMEM);
    cudaFuncSetAttribute(hgemm<3>, cudaFuncAttributeMaxDynamicSharedMemorySize, GEMM_SMEM);

    // 0. weight transpose+convert to fp16 [N,K] (single batched launch)
    transpose_all<<<TT_TOTAL, dim3(32, 8)>>>(w_attn, w_proj, w_fc, w_out,
                                             wt_attn, wt_proj, wt_fc, wt_out);

    // 1. h = LN1(x) -> fp16
    ln_kernel<<<ROWS, 256>>>(x, ln1_g, ln1_b, h16);
    // 2. qkv GEMM, fused split epilogue:
    //    Q -> q16 (fp16, x0.125), K/V -> present (fp32) + kv16 (fp16)
    hgemm<3><<<dim3(3*DMODEL/256, ROWS/128), 512, GEMM_SMEM>>>(
        h16, wt_attn, b_attn, nullptr, present, q16, kv16, ROWS, 3*DMODEL, DMODEL);
    // 3. attention -> attn16  [L,B,D] fp16
    attn_kernel<<<dim3(SEQ / 128, NH, BATCH), 256, ATTN_SMEM>>>(q16, kv16, attn16);
    // 4. x1 = x + attn @ w_proj + b_proj (fp32 out)
    hgemm<1><<<dim3(DMODEL/256, ROWS/128), 512, GEMM_SMEM>>>(
        attn16, wt_proj, b_proj, x, x1, nullptr, nullptr, ROWS, DMODEL, DMODEL);
    // 5. h2 = LN2(x1) -> fp16
    ln_kernel<<<ROWS, 256>>>(x1, ln2_g, ln2_b, h2_16);
    // 6. m = gelu(h2 @ w_fc + b_fc) -> fp16
    hgemm<2><<<dim3(DFF/256, ROWS/128), 512, GEMM_SMEM>>>(
        h2_16, wt_fc, b_fc, nullptr, nullptr, m16, nullptr, ROWS, DFF, DMODEL);
    // 7. out_x = x1 + m @ w_out + b_out (fp32 out)
    hgemm<1><<<dim3(DMODEL/256, ROWS/128), 512, GEMM_SMEM>>>(
        m16, wt_out, b_out, x1, out, nullptr, nullptr, ROWS, DMODEL, DFF);
}

// round 17
// speedup vs baseline: 1.0550x; 1.0550x over previous
#include <cuda_runtime.h>
#include <cuda_fp16.h>
#include <math.h>
#include <stdint.h>

#define SEQ    2048
#define BATCH  2
#define DMODEL 1024
#define NH     16
#define HD     64
#define DFF    4096
#define ROWS   (SEQ*BATCH)   // 4096

// ---------------- scratch (device globals; no allocation allowed) ----------
__device__ __half g_h16  [ROWS*DMODEL];      // LN1 out (fp16)
__device__ __half g_q16  [ROWS*DMODEL];      // Q (fp16, pre-scaled by 1/8)
__device__ __half g_kv16 [2*BATCH*NH*SEQ*HD];// K,V fp16 copy [2,B,H,L,hd]
__device__ __half g_attn16[ROWS*DMODEL];     // attention out (fp16)
__device__ float  g_x1   [ROWS*DMODEL];      // x + attn_proj (fp32)
__device__ __half g_h2_16[ROWS*DMODEL];      // LN2 out (fp16)
__device__ __half g_m16  [ROWS*DFF];         // gelu(fc) out (fp16)
// transposed fp16 weights [N,K]
__device__ __half g_wt_attn[3*DMODEL*DMODEL];
__device__ __half g_wt_proj[DMODEL*DMODEL];
__device__ __half g_wt_fc  [DFF*DMODEL];
__device__ __half g_wt_out [DMODEL*DFF];

// ---------------- helpers ----------------------------------------------------
__device__ __forceinline__ uint32_t smem_u32(const void* p)
{
    return (uint32_t)__cvta_generic_to_shared(p);
}

__device__ __forceinline__ void cp16(uint32_t dst, const void* src)
{
    asm volatile("cp.async.cg.shared.global [%0], [%1], 16;" :: "r"(dst), "l"(src) : "memory");
}

__device__ __forceinline__ void ldsm_x4(uint32_t* r, uint32_t addr)
{
    asm volatile("ldmatrix.sync.aligned.m8n8.x4.shared.b16 {%0,%1,%2,%3}, [%4];"
                 : "=r"(r[0]), "=r"(r[1]), "=r"(r[2]), "=r"(r[3]) : "r"(addr));
}

__device__ __forceinline__ void ldsm_x4t(uint32_t* r, uint32_t addr)
{
    asm volatile("ldmatrix.sync.aligned.m8n8.x4.trans.shared.b16 {%0,%1,%2,%3}, [%4];"
                 : "=r"(r[0]), "=r"(r[1]), "=r"(r[2]), "=r"(r[3]) : "r"(addr));
}

__device__ __forceinline__ void mma16816(float* c, const uint32_t* a, const uint32_t* b)
{
    asm volatile(
        "mma.sync.aligned.m16n8k16.row.col.f32.f16.f16.f32 "
        "{%0,%1,%2,%3}, {%4,%5,%6,%7}, {%8,%9}, {%0,%1,%2,%3};\n"
        : "+f"(c[0]), "+f"(c[1]), "+f"(c[2]), "+f"(c[3])
        : "r"(a[0]), "r"(a[1]), "r"(a[2]), "r"(a[3]),
          "r"(b[0]), "r"(b[1]));
}

__device__ __forceinline__ uint32_t pack_h2(float a, float b)
{
    __half2 h = __floats2half2_rn(a, b);
    return *reinterpret_cast<uint32_t*>(&h);
}

__device__ __forceinline__ float gelu_f(float v)
{
    float c = v + 0.044715f * v * v * v;
    return 0.5f * v * (1.0f + tanhf(0.7978845608028654f * c));
}

// ---------------- batched weight transpose+convert --------------------------
#define TT_TOTAL 12288
__global__ void transpose_all(const float* __restrict__ w0, const float* __restrict__ w1,
                              const float* __restrict__ w2, const float* __restrict__ w3,
                              __half* __restrict__ t0, __half* __restrict__ t1,
                              __half* __restrict__ t2, __half* __restrict__ t3)
{
    __shared__ float t[32][33];
    int tb = blockIdx.x;
    const float* W; __half* Wt; int K, N, ntx, local;
    if (tb < 3072)      { W = w0; Wt = t0; K = DMODEL; N = 3*DMODEL; ntx = 96;  local = tb; }
    else if (tb < 4096) { W = w1; Wt = t1; K = DMODEL; N = DMODEL;   ntx = 32;  local = tb - 3072; }
    else if (tb < 8192) { W = w2; Wt = t2; K = DMODEL; N = DFF;      ntx = 128; local = tb - 4096; }
    else                { W = w3; Wt = t3; K = DFF;    N = DMODEL;   ntx = 32;  local = tb - 8192; }
    int n0 = (local % ntx) * 32, k0 = (local / ntx) * 32;
    int tx = threadIdx.x, ty = threadIdx.y;
    #pragma unroll
    for (int d = 0; d < 32; d += 8)
        t[ty + d][tx] = W[(size_t)(k0 + ty + d) * N + n0 + tx];
    __syncthreads();
    #pragma unroll
    for (int d = 0; d < 32; d += 8)
        Wt[(size_t)(n0 + ty + d) * K + k0 + tx] = __float2half_rn(t[tx][ty + d]);
}

// ---------------- LayerNorm: one CTA per row, fp16 output ------------------
__global__ void ln_kernel(const float* __restrict__ x,
                          const float* __restrict__ g,
                          const float* __restrict__ b,
                          __half* __restrict__ y)
{
    int row = blockIdx.x;
    int tid = threadIdx.x;
    const float4* xr = reinterpret_cast<const float4*>(x + (size_t)row * DMODEL);
    float4 v = xr[tid];

    __shared__ float red[8];
    __shared__ float stat[2];

    float s = v.x + v.y + v.z + v.w;
    #pragma unroll
    for (int o = 16; o; o >>= 1) s += __shfl_xor_sync(0xffffffffu, s, o);
    if ((tid & 31) == 0) red[tid >> 5] = s;
    __syncthreads();
    if (tid == 0) {
        float t = 0.f;
        #pragma unroll
        for (int i = 0; i < 8; i++) t += red[i];
        stat[0] = t * (1.0f / DMODEL);
    }
    __syncthreads();
    float mu = stat[0];

    float dx = v.x - mu, dy = v.y - mu, dz = v.z - mu, dw = v.w - mu;
    float s2 = dx*dx + dy*dy + dz*dz + dw*dw;
    #pragma unroll
    for (int o = 16; o; o >>= 1) s2 += __shfl_xor_sync(0xffffffffu, s2, o);
    if ((tid & 31) == 0) red[tid >> 5] = s2;
    __syncthreads();
    if (tid == 0) {
        float t = 0.f;
        #pragma unroll
        for (int i = 0; i < 8; i++) t += red[i];
        stat[1] = rsqrtf(t * (1.0f / DMODEL) + 1e-5f);
    }
    __syncthreads();
    float rstd = stat[1];

    const float4* gr = reinterpret_cast<const float4*>(g);
    const float4* br = reinterpret_cast<const float4*>(b);
    float4 gv = gr[tid], bv = br[tid];
    __half2 p0 = __floats2half2_rn(dx * rstd * gv.x + bv.x, dy * rstd * gv.y + bv.y);
    __half2 p1 = __floats2half2_rn(dz * rstd * gv.z + bv.z, dw * rstd * gv.w + bv.w);
    __half2* yr = reinterpret_cast<__half2*>(y + (size_t)row * DMODEL);
    yr[tid * 2 + 0] = p0;
    yr[tid * 2 + 1] = p1;
}

// ---------------- fp16 mma.sync GEMM ----------------------------------------
// C[M,N] = A[M,K]f16 @ Bt[N,K]f16^T + epilogue, fp32 accum.
// 128x256 CTA tile, BK=32 halves, 4-stage cp.async ring, single sync/iter.
// 512 threads = 16 warps (2x8); warp tile 64x32 = 4m x 4n of m16n8k16.
// EPI: 0 = +bias (f32 out), 1 = +bias+res (f32 out), 2 = gelu(+bias) (f16 out)
// EPI 3 = qkv split: Q -> Ch (fp16, x0.125), K/V -> Cf (present fp32) + kvh (fp16)
#define BK        32
#define KROW      40                        // BK + 8 pad (halves); 80B stride
#define A_STAGE_B (128*KROW*2)              // 10240 bytes
#define B_STAGE_B (256*KROW*2)              // 20480 bytes
#define STAGE_B   (A_STAGE_B + B_STAGE_B)   // 30720 bytes
#define GSTAGES   4
#define GEMM_SMEM (GSTAGES*STAGE_B)         // 122880

template<int EPI>
__global__ void __launch_bounds__(512, 1)
hgemm(const __half* __restrict__ A, const __half* __restrict__ Bt,
      const float* __restrict__ bias, const float* __restrict__ res,
      float* __restrict__ Cf, __half* __restrict__ Ch,
      __half* __restrict__ kvh,
      int M, int N, int K)
{
    extern __shared__ char smem_raw[];
    uint32_t sbase = smem_u32(smem_raw);

    int tid = threadIdx.x;
    int w = tid >> 5, lane = tid & 31;
    int lr = lane >> 2, lc = lane & 3;
    int wm = w >> 3, wn = w & 7;                 // 2 x 8 warp grid
    int row0 = blockIdx.y * 128, col0 = blockIdx.x * 256;
    int KT = K / BK;

    float acc[4][4][4];
    #pragma unroll
    for (int i = 0; i < 4; ++i)
        #pragma unroll
        for (int j = 0; j < 4; ++j)
            acc[i][j][0] = acc[i][j][1] = acc[i][j][2] = acc[i][j][3] = 0.f;

    int ar = tid >> 2, seg = tid & 3;
    const char* Asrc  = (const char*)(A + (size_t)(row0 + ar) * K + seg * 8);
    const char* Bsrc0 = (const char*)(Bt + (size_t)(col0 + ar) * K + seg * 8);
    const char* Bsrc1 = (const char*)(Bt + (size_t)(col0 + ar + 128) * K + seg * 8);
    uint32_t dA  = (uint32_t)(ar * KROW + seg * 8) * 2;
    uint32_t dB1 = dA + (uint32_t)(128 * KROW) * 2;

    int g = lane >> 3;   // 0..3
    uint32_t aFrag[2], bFrag[2];
    #pragma unroll
    for (int kk = 0; kk < 2; ++kk) {
        aFrag[kk] = (uint32_t)((wm * 64 + (lane & 15)) * KROW + kk * 16 + (lane >> 4) * 8) * 2;
        bFrag[kk] = (uint32_t)A_STAGE_B +
                    (uint32_t)((wn * 32 + (g >> 1) * 8 + (lane & 7)) * KROW
                               + kk * 16 + (g & 1) * 8) * 2;
    }

    auto load_stage = [&](int slot, int kc) {
        uint32_t ab = sbase + slot * STAGE_B;
        uint32_t bb = ab + A_STAGE_B;
        size_t koff = (size_t)kc * BK * 2;
        cp16(ab + dA,  Asrc  + koff);
        cp16(bb + dA,  Bsrc0 + koff);
        cp16(bb + dB1, Bsrc1 + koff);
    };

    #pragma unroll
    for (int c = 0; c < GSTAGES - 1; ++c) {
        load_stage(c, c);
        asm volatile("cp.async.commit_group;" ::: "memory");
    }

    for (int i = 0; i < KT; ++i) {
        asm volatile("cp.async.wait_group %0;" :: "n"(GSTAGES - 2) : "memory");
        __syncthreads();                           // single barrier per iter

        if (i + GSTAGES - 1 < KT)
            load_stage((i + GSTAGES - 1) & (GSTAGES - 1), i + GSTAGES - 1);
        asm volatile("cp.async.commit_group;" ::: "memory");

        uint32_t stg = sbase + (i & (GSTAGES - 1)) * STAGE_B;
        #pragma unroll
        for (int kk = 0; kk < 2; ++kk) {
            uint32_t af[4][4], bf[2][4];
            #pragma unroll
            for (int mi = 0; mi < 4; ++mi)
                ldsm_x4(af[mi], stg + aFrag[kk] + (uint32_t)(mi * 16 * KROW) * 2);
            #pragma unroll
            for (int nb = 0; nb < 2; ++nb)
                ldsm_x4(bf[nb], stg + bFrag[kk] + (uint32_t)(nb * 16 * KROW) * 2);
            #pragma unroll
            for (int mi = 0; mi < 4; ++mi)
                #pragma unroll
                for (int nb = 0; nb < 2; ++nb) {
                    mma16816(acc[mi][2*nb],   af[mi], &bf[nb][0]);
                    mma16816(acc[mi][2*nb+1], af[mi], &bf[nb][2]);
                }
        }
    }

    int sect = col0 >> 10;   // EPI==3: constant per tile (256 | 1024)

    #pragma unroll
    for (int mi = 0; mi < 4; ++mi) {
        #pragma unroll
        for (int hh = 0; hh < 2; ++hh) {
            int r = row0 + wm * 64 + mi * 16 + lr + hh * 8;
            #pragma unroll
            for (int ni = 0; ni < 4; ++ni) {
                int c = col0 + wn * 32 + ni * 8 + 2 * lc;
                float2 bv = *(const float2*)&bias[c];
                float ox = acc[mi][ni][2 * hh + 0] + bv.x;
                float oy = acc[mi][ni][2 * hh + 1] + bv.y;
                if (EPI == 1) {
                    float2 rv = *(const float2*)&res[(size_t)r * N + c];
                    ox += rv.x; oy += rv.y;
                }
                if (EPI == 2) {
                    *(__half2*)&Ch[(size_t)r * N + c] =
                        __floats2half2_rn(gelu_f(ox), gelu_f(oy));
                } else if (EPI == 3) {
                    if (sect == 0) {
                        *(__half2*)&Ch[(size_t)r * DMODEL + c] =
                            __floats2half2_rn(ox * 0.125f, oy * 0.125f);
                    } else {
                        int d  = c & (DMODEL - 1);
                        int hh2 = d >> 6, hd = d & (HD - 1);
                        int l = r >> 1, bb = r & 1;
                        size_t pidx = ((((size_t)(sect - 1) * BATCH + bb) * NH + hh2) * SEQ + l) * HD + hd;
                        *(float2*)&Cf[pidx] = make_float2(ox, oy);
                        *(__half2*)&kvh[pidx] = __floats2half2_rn(ox, oy);
                    }
                } else {
                    *(float2*)&Cf[(size_t)r * N + c] = make_float2(ox, oy);
                }
            }
        }
    }
}

// ---------------- Flash attention (fp16 mma.m16n8k16, register P) ----------
// CTA: 256 queries x (head, batch), 512 threads = 16 warps; warp w owns query
// rows 16w..16w+15. One shared KV stream per 256 queries (half the cp.async
// traffic of the previous 128q/256t version), triple-buffered.
#define AQP   72                         // row pitch (halves) = 144B
#define KVBUF (64*AQP)                   // halves per K (or V) tile
#define NBUF  3
#define QROWS 256
#define ATTN_SMEM ((QROWS*AQP + NBUF*2*KVBUF) * 2)
#define NKB   (SEQ/64)

__global__ void __launch_bounds__(512, 1)
attn_kernel(const __half* __restrict__ q16, const __half* __restrict__ kv16,
            __half* __restrict__ out)
{
    extern __shared__ __half sh[];
    __half* sQ  = sh;                    // QROWS x AQP
    __half* sKV = sh + QROWS * AQP;      // NBUF x (K 64xAQP, V 64xAQP)

    int tid  = threadIdx.x;
    int w = tid >> 5, lane = tid & 31;
    int lr = lane >> 2, lc = lane & 3;
    int bq = blockIdx.x, h = blockIdx.y, b = blockIdx.z;

    const __half* Kg = kv16 + ((size_t)b * NH + h) * SEQ * HD;
    const __half* Vg = kv16 + (((size_t)BATCH + b) * NH + h) * SEQ * HD;

    // Q loads: 256 rows x 8 segs = 2048 chunks, 4 per thread
    #pragma unroll
    for (int i = 0; i < 4; ++i) {
        int ck = i * 512 + tid;
        int r = ck >> 3, seg = ck & 7;
        cp16(smem_u32(sQ + r * AQP + seg * 8),
             q16 + (((size_t)(bq * QROWS + r) * BATCH + b) * DMODEL + h * HD + seg * 8));
    }
    asm volatile("cp.async.commit_group;" ::: "memory");

    // KV loads: K 512 chunks + V 512 chunks = 2 per thread
    auto load_kv = [&](int kb, int buf) {
        __half* Kb = sKV + buf * 2 * KVBUF;
        __half* Vb = Kb + KVBUF;
        int r = tid >> 3, seg = tid & 7;
        cp16(smem_u32(Kb + r * AQP + seg * 8),
             Kg + (size_t)(kb * 64 + r) * HD + seg * 8);
        cp16(smem_u32(Vb + r * AQP + seg * 8),
             Vg + (size_t)(kb * 64 + r) * HD + seg * 8);
    };

    load_kv(0, 0);
    asm volatile("cp.async.commit_group;" ::: "memory");
    load_kv(1, 1);
    asm volatile("cp.async.commit_group;" ::: "memory");

    asm volatile("cp.async.wait_group 2;" ::: "memory");
    __syncthreads();
    uint32_t qa[4][4];
    #pragma unroll
    for (int kk = 0; kk < 4; ++kk)
        ldsm_x4(qa[kk], smem_u32(sQ + ((w * 16 + (lane & 15)) * AQP
                                       + kk * 16 + (lane >> 4) * 8)));

    // x4 fragment offsets (lane-group trick)
    uint32_t kOff[4], vOff[4];
    {
        int gHi = (lane >> 4);        // g>>1
        int gLo = (lane >> 3) & 1;    // g&1
        #pragma unroll
        for (int kk = 0; kk < 4; ++kk)
            kOff[kk] = (uint32_t)((gHi * 8 + (lane & 7)) * AQP + kk * 16 + gLo * 8) * 2;
        #pragma unroll
        for (int kk = 0; kk < 4; ++kk)
            vOff[kk] = (uint32_t)((kk * 16 + gLo * 8 + (lane & 7)) * AQP + gHi * 8) * 2;
    }

    float mrow[2] = {-1e30f, -1e30f};
    float lrow[2] = {0.f, 0.f};
    float O[8][4];
    #pragma unroll
    for (int ni = 0; ni < 8; ++ni)
        O[ni][0] = O[ni][1] = O[ni][2] = O[ni][3] = 0.f;

    int buf = 0, nbuf = 2;
    for (int kb = 0; kb < NKB; ++kb) {
        asm volatile("cp.async.wait_group 1;" ::: "memory");
        __syncthreads();

        if (kb + 2 < NKB) load_kv(kb + 2, nbuf);
        asm volatile("cp.async.commit_group;" ::: "memory");

        uint32_t Kb = smem_u32(sKV + buf * 2 * KVBUF);
        uint32_t Vb = Kb + KVBUF * 2;

        // S = Q @ K^T : 4 kk x 4 n-pairs, x4 K loads
        float S[8][4];
        #pragma unroll
        for (int ni = 0; ni < 8; ++ni)
            S[ni][0] = S[ni][1] = S[ni][2] = S[ni][3] = 0.f;
        #pragma unroll
        for (int kk = 0; kk < 4; ++kk) {
            #pragma unroll
            for (int nip = 0; nip < 4; ++nip) {
                uint32_t kf[4];
                ldsm_x4(kf, Kb + kOff[kk] + (uint32_t)(nip * 16 * AQP) * 2);
                mma16816(S[2*nip],   qa[kk], &kf[0]);
                mma16816(S[2*nip+1], qa[kk], &kf[2]);
            }
        }

        #pragma unroll
        for (int hh = 0; hh < 2; ++hh) {
            float mx = -1e30f;
            #pragma unroll
            for (int ni = 0; ni < 8; ++ni)
                mx = fmaxf(mx, fmaxf(S[ni][2*hh], S[ni][2*hh+1]));
            mx = fmaxf(mx, __shfl_xor_sync(0xffffffffu, mx, 1));
            mx = fmaxf(mx, __shfl_xor_sync(0xffffffffu, mx, 2));
            float nm = fmaxf(mrow[hh], mx);
            float corr = __expf(mrow[hh] - nm);
            mrow[hh] = nm;
            float rs = 0.f;
            #pragma unroll
            for (int ni = 0; ni < 8; ++ni) {
                float p0 = __expf(S[ni][2*hh]   - nm);
                float p1 = __expf(S[ni][2*hh+1] - nm);
                S[ni][2*hh] = p0; S[ni][2*hh+1] = p1;
                rs += p0 + p1;
            }
            rs += __shfl_xor_sync(0xffffffffu, rs, 1);
            rs += __shfl_xor_sync(0xffffffffu, rs, 2);
            lrow[hh] = lrow[hh] * corr + rs;
            #pragma unroll
            for (int ni = 0; ni < 8; ++ni) {
                O[ni][2*hh]   *= corr;
                O[ni][2*hh+1] *= corr;
            }
        }

        // O += P @ V : x4.trans V loads
        #pragma unroll
        for (int kk = 0; kk < 4; ++kk) {
            uint32_t pa[4];
            pa[0] = pack_h2(S[2*kk][0],   S[2*kk][1]);
            pa[1] = pack_h2(S[2*kk][2],   S[2*kk][3]);
            pa[2] = pack_h2(S[2*kk+1][0], S[2*kk+1][1]);
            pa[3] = pack_h2(S[2*kk+1][2], S[2*kk+1][3]);
            #pragma unroll
            for (int nip = 0; nip < 4; ++nip) {
                uint32_t vf[4];
                ldsm_x4t(vf, Vb + vOff[kk] + (uint32_t)(nip * 16) * 2);
                mma16816(O[2*nip],   pa, &vf[0]);
                mma16816(O[2*nip+1], pa, &vf[2]);
            }
        }

        buf  = (buf == NBUF - 1) ? 0 : buf + 1;
        nbuf = (nbuf == NBUF - 1) ? 0 : nbuf + 1;
    }

    #pragma unroll
    for (int hh = 0; hh < 2; ++hh) {
        int r = w * 16 + lr + hh * 8;
        int l = bq * QROWS + r;
        float inv = 1.0f / lrow[hh];
        __half* po = out + (size_t)(l * BATCH + b) * DMODEL + h * HD;
        #pragma unroll
        for (int ni = 0; ni < 8; ++ni)
            *(__half2*)&po[ni * 8 + 2 * lc] =
                __floats2half2_rn(O[ni][2*hh] * inv, O[ni][2*hh+1] * inv);
    }
}

// ---------------- launcher --------------------------------------------------
extern "C" void kernel_launch(void* const* d_in, const int* in_sizes, int n_in,
                              void* d_out, int out_size)
{
    const float* x      = (const float*)d_in[0];
    const float* ln1_g  = (const float*)d_in[1];
    const float* ln1_b  = (const float*)d_in[2];
    const float* w_attn = (const float*)d_in[3];
    const float* b_attn = (const float*)d_in[4];
    const float* w_proj = (const float*)d_in[5];
    const float* b_proj = (const float*)d_in[6];
    const float* ln2_g  = (const float*)d_in[7];
    const float* ln2_b  = (const float*)d_in[8];
    const float* w_fc   = (const float*)d_in[9];
    const float* b_fc   = (const float*)d_in[10];
    const float* w_out  = (const float*)d_in[11];
    const float* b_out  = (const float*)d_in[12];

    float* out     = (float*)d_out;
    float* present = out + (size_t)SEQ * BATCH * DMODEL;

    __half *h16, *q16, *kv16, *attn16, *h2_16, *m16;
    __half *wt_attn, *wt_proj, *wt_fc, *wt_out;
    float *x1;
    cudaGetSymbolAddress((void**)&h16,     g_h16);
    cudaGetSymbolAddress((void**)&q16,     g_q16);
    cudaGetSymbolAddress((void**)&kv16,    g_kv16);
    cudaGetSymbolAddress((void**)&attn16,  g_attn16);
    cudaGetSymbolAddress((void**)&x1,      g_x1);
    cudaGetSymbolAddress((void**)&h2_16,   g_h2_16);
    cudaGetSymbolAddress((void**)&m16,     g_m16);
    cudaGetSymbolAddress((void**)&wt_attn, g_wt_attn);
    cudaGetSymbolAddress((void**)&wt_proj, g_wt_proj);
    cudaGetSymbolAddress((void**)&wt_fc,   g_wt_fc);
    cudaGetSymbolAddress((void**)&wt_out,  g_wt_out);

    cudaFuncSetAttribute(attn_kernel, cudaFuncAttributeMaxDynamicSharedMemorySize, ATTN_SMEM);
    cudaFuncSetAttribute(hgemm<0>, cudaFuncAttributeMaxDynamicSharedMemorySize, GEMM_SMEM);
    cudaFuncSetAttribute(hgemm<1>, cudaFuncAttributeMaxDynamicSharedMemorySize, GEMM_SMEM);
    cudaFuncSetAttribute(hgemm<2>, cudaFuncAttributeMaxDynamicSharedMemorySize, GEMM_SMEM);
    cudaFuncSetAttribute(hgemm<3>, cudaFuncAttributeMaxDynamicSharedMemorySize, GEMM_SMEM);

    // 0. weight transpose+convert to fp16 [N,K] (single batched launch)
    transpose_all<<<TT_TOTAL, dim3(32, 8)>>>(w_attn, w_proj, w_fc, w_out,
                                             wt_attn, wt_proj, wt_fc, wt_out);

    // 1. h = LN1(x) -> fp16
    ln_kernel<<<ROWS, 256>>>(x, ln1_g, ln1_b, h16);
    // 2. qkv GEMM, fused split epilogue:
    //    Q -> q16 (fp16, x0.125), K/V -> present (fp32) + kv16 (fp16)
    hgemm<3><<<dim3(3*DMODEL/256, ROWS/128), 512, GEMM_SMEM>>>(
        h16, wt_attn, b_attn, nullptr, present, q16, kv16, ROWS, 3*DMODEL, DMODEL);
    // 3. attention -> attn16  [L,B,D] fp16
    attn_kernel<<<dim3(SEQ / QROWS, NH, BATCH), 512, ATTN_SMEM>>>(q16, kv16, attn16);
    // 4. x1 = x + attn @ w_proj + b_proj (fp32 out)
    hgemm<1><<<dim3(DMODEL/256, ROWS/128), 512, GEMM_SMEM>>>(
        attn16, wt_proj, b_proj, x, x1, nullptr, nullptr, ROWS, DMODEL, DMODEL);
    // 5. h2 = LN2(x1) -> fp16
    ln_kernel<<<ROWS, 256>>>(x1, ln2_g, ln2_b, h2_16);
    // 6. m = gelu(h2 @ w_fc + b_fc) -> fp16
    hgemm<2><<<dim3(DFF/256, ROWS/128), 512, GEMM_SMEM>>>(
        h2_16, wt_fc, b_fc, nullptr, nullptr, m16, nullptr, ROWS, DFF, DMODEL);
    // 7. out_x = x1 + m @ w_out + b_out (fp32 out)
    hgemm<1><<<dim3(DMODEL/256, ROWS/128), 512, GEMM_SMEM>>>(
        m16, wt_out, b_out, x1, out, nullptr, nullptr, ROWS, DMODEL, DFF);
}